// round 16
// baseline (speedup 1.0000x reference)
#include <cuda_runtime.h>
#include <cuda_fp16.h>
#include <cstdint>
#include <math.h>

// ---------------- problem constants ----------------
#define BATCH   8
#define GH      40
#define GW      40
#define MPIL    (BATCH*GH*GW)      // 12800 pillars
#define NPTS    32
#define CIN     6
#define CF      256
#define NFEAT   12

#define M1      800
#define MPAD    896                // padded M for guard-free loads
#define N1      1024
#define K1      2304               // 9 taps * 256
#define N2      4096
#define K2      1024
#define OUT_MAIN (M1*N2)           // 3276800

#define NPFN    (MPIL/2)           // 6400 pfn blocks (2 pillars each)
#define NW2B    (N2*K2/4/256)      // 4096 w2-convert blocks

// ---------------- device scratch ----------------
__device__ __half  g_canvas_h[MPIL*CF];   // NHWC fp16 canvas
__device__ __half  g_B1[N1*K1];
__device__ __half  g_A2[MPAD*K2];
__device__ __half  g_B2[N2*K2];
__device__ float   g_rowsum[M1];

// ================= helpers =================
__device__ __forceinline__ uint32_t smem_to_u32(const void* p) {
    uint32_t a;
    asm("{ .reg .u64 t; cvta.to.shared.u64 t, %1; cvt.u32.u64 %0, t; }" : "=r"(a) : "l"(p));
    return a;
}
#define SWZ(x) ((uint32_t)(x) ^ (((uint32_t)(x) >> 3) & 0x70))

__device__ __forceinline__ void cpa16(uint32_t dst, const void* src) {
    asm volatile("cp.async.cg.shared.global [%0], [%1], 16;"
                 :: "r"(dst), "l"(src) : "memory");
}
__device__ __forceinline__ void cpa16p(uint32_t dst, const void* src, uint32_t srcsize) {
    asm volatile("cp.async.cg.shared.global [%0], [%1], 16, %2;"
                 :: "r"(dst), "l"(src), "r"(srcsize) : "memory");
}
#define CP_COMMIT() asm volatile("cp.async.commit_group;" ::: "memory")

__device__ __forceinline__ void ldsm4(uint32_t* r, uint32_t addr) {
    asm volatile("ldmatrix.sync.aligned.m8n8.x4.shared.b16 {%0,%1,%2,%3}, [%4];"
        : "=r"(r[0]), "=r"(r[1]), "=r"(r[2]), "=r"(r[3]) : "r"(addr));
}
__device__ __forceinline__ void mma16816(float* d, const uint32_t* a, const uint32_t* b) {
    asm volatile(
        "mma.sync.aligned.m16n8k16.row.col.f32.f16.f16.f32 "
        "{%0,%1,%2,%3}, {%4,%5,%6,%7}, {%8,%9}, {%0,%1,%2,%3};"
        : "+f"(d[0]), "+f"(d[1]), "+f"(d[2]), "+f"(d[3])
        : "r"(a[0]), "r"(a[1]), "r"(a[2]), "r"(a[3]), "r"(b[0]), "r"(b[1]));
}

// packed fp32x2 (sm_100+ family feature, legal at compute_103)
#define PACK2(out, lo, hi)  asm("mov.b64 %0, {%1, %2};" : "=l"(out) : "f"(lo), "f"(hi))
#define UNPACK2(lo, hi, in) asm("mov.b64 {%0, %1}, %2;" : "=f"(lo), "=f"(hi) : "l"(in))
#define FMA2(acc, a, b)     asm("fma.rn.f32x2 %0, %1, %2, %0;" : "+l"(acc) : "l"(a), "l"(b))

// ================= fused front end: PFN + w1 transpose + w2 convert ======
__global__ __launch_bounds__(256) void fused_pre(
    const float* __restrict__ voxels, const int* __restrict__ num_points,
    const int* __restrict__ coors,    const float* __restrict__ w,
    const float* __restrict__ bn_gamma, const float* __restrict__ bn_beta,
    const float* __restrict__ bn_mean,  const float* __restrict__ bn_var,
    const float* __restrict__ w1, const float* __restrict__ w2)
{
    __shared__ __align__(16) float sbuf[K1];   // w1: full row; pfn: dup-feats+smean
    int blk = blockIdx.x;

    if (blk < NPFN) {
        // ---- PFN ----
        // feats stored DUPLICATED as float2 {v,v}: [sub][n][12 float2] = 24 floats/n
        float* feats = sbuf;             // sub*768 + n*24
        float* smean = sbuf + 1536;      // [sub*3 + j]
        int sub = threadIdx.x >> 7;
        int f   = threadIdx.x & 127;
        int m   = blk*2 + sub;

        int np = num_points[m];
        const float* vox = voxels + (size_t)m * NPTS * CIN;

        float x=0.f, y=0.f, z=0.f, msk=0.f;
        if (f < NPTS) {
            int n = f;
            msk = (n < np) ? 1.0f : 0.0f;
            x = vox[n*CIN+0]; y = vox[n*CIN+1]; z = vox[n*CIN+2];
            float mx=x*msk, my=y*msk, mz=z*msk;
            #pragma unroll
            for (int o = 16; o; o >>= 1) {
                mx += __shfl_xor_sync(0xffffffffu, mx, o);
                my += __shfl_xor_sync(0xffffffffu, my, o);
                mz += __shfl_xor_sync(0xffffffffu, mz, o);
            }
            if (n == 0) {
                float inv = 1.0f / (float)np;
                smean[sub*3+0]=mx*inv; smean[sub*3+1]=my*inv; smean[sub*3+2]=mz*inv;
            }
        }
        __syncthreads();
        if (f < NPTS) {
            int n = f;
            float cx = (float)coors[m*4+3]*0.025f + (0.0125f - 0.5f);
            float cy = (float)coors[m*4+2]*0.025f + (0.0125f - 0.5f);
            float cz = (float)coors[m*4+1]*1.0f + 0.5f;
            float2* fr = (float2*)(feats + sub*768 + n*24);
            float v;
            v = x*msk;               fr[0]  = make_float2(v, v);
            v = y*msk;               fr[1]  = make_float2(v, v);
            v = z*msk;               fr[2]  = make_float2(v, v);
            v = vox[n*CIN+3]*msk;    fr[3]  = make_float2(v, v);
            v = vox[n*CIN+4]*msk;    fr[4]  = make_float2(v, v);
            v = vox[n*CIN+5]*msk;    fr[5]  = make_float2(v, v);
            v = (x-smean[sub*3+0])*msk; fr[6]  = make_float2(v, v);
            v = (y-smean[sub*3+1])*msk; fr[7]  = make_float2(v, v);
            v = (z-smean[sub*3+2])*msk; fr[8]  = make_float2(v, v);
            v = (x-cx)*msk;          fr[9]  = make_float2(v, v);
            v = (y-cy)*msk;          fr[10] = make_float2(v, v);
            v = (z-cz)*msk;          fr[11] = make_float2(v, v);
        }
        __syncthreads();

        int f1 = f + 128;
        float sc0 = bn_gamma[f]  * rsqrtf(bn_var[f]  + 1e-3f);
        float sc1 = bn_gamma[f1] * rsqrtf(bn_var[f1] + 1e-3f);
        float bt0 = bn_beta[f]  - bn_mean[f]  * sc0;
        float bt1 = bn_beta[f1] - bn_mean[f1] * sc1;
        unsigned long long w2v[NFEAT], bt2;
        #pragma unroll
        for (int d = 0; d < NFEAT; d++)
            PACK2(w2v[d], w[d*CF + f] * sc0, w[d*CF + f1] * sc1);
        PACK2(bt2, bt0, bt1);

        float vmax0 = (np < NPTS) ? fmaxf(bt0, 0.f) : 0.f;
        float vmax1 = (np < NPTS) ? fmaxf(bt1, 0.f) : 0.f;
        const ulonglong2* fb = (const ulonglong2*)(feats + sub*768);
        #pragma unroll 2
        for (int n = 0; n < np; n++) {
            const ulonglong2* row = fb + n*6;   // 6 x 16B per point
            unsigned long long acc = bt2;
            ulonglong2 v0 = row[0], v1 = row[1], v2 = row[2];
            FMA2(acc, v0.x, w2v[0]);  FMA2(acc, v0.y, w2v[1]);
            FMA2(acc, v1.x, w2v[2]);  FMA2(acc, v1.y, w2v[3]);
            FMA2(acc, v2.x, w2v[4]);  FMA2(acc, v2.y, w2v[5]);
            ulonglong2 v3 = row[3], v4 = row[4], v5 = row[5];
            FMA2(acc, v3.x, w2v[6]);  FMA2(acc, v3.y, w2v[7]);
            FMA2(acc, v4.x, w2v[8]);  FMA2(acc, v4.y, w2v[9]);
            FMA2(acc, v5.x, w2v[10]); FMA2(acc, v5.y, w2v[11]);
            float h0, h1; UNPACK2(h0, h1, acc);
            vmax0 = fmaxf(vmax0, h0);
            vmax1 = fmaxf(vmax1, h1);
        }

        int b = coors[m*4+0], yy = coors[m*4+2], xx = coors[m*4+3];
        size_t px = (((size_t)b*GH + yy)*GW + xx)*CF;
        g_canvas_h[px + f]  = __float2half_rn(vmax0);
        g_canvas_h[px + f1] = __float2half_rn(vmax1);
    } else if (blk < NPFN + N1) {
        // ---- w1 transpose ----
        int o = blk - NPFN;
        const float* src = w1 + (size_t)o*K1;
        #pragma unroll
        for (int i = threadIdx.x; i < K1; i += 256) sbuf[i] = src[i];
        __syncthreads();
        #pragma unroll
        for (int i = threadIdx.x; i < K1; i += 256) {
            int tap = i >> 8, ci = i & 255;
            g_B1[(size_t)o*K1 + i] = __float2half_rn(sbuf[ci*9 + tap]);
        }
    } else {
        // ---- w2 convert (+ rowsum clear) ----
        int rb = blk - NPFN - N1;
        int t = rb*256 + threadIdx.x;
        if (t < N2*K2/4) {
            float4 v = *(const float4*)(w2 + (size_t)t*4);
            __half h[4];
            h[0]=__float2half_rn(v.x); h[1]=__float2half_rn(v.y);
            h[2]=__float2half_rn(v.z); h[3]=__float2half_rn(v.w);
            *(uint2*)(g_B2 + (size_t)t*4) = *(uint2*)h;
        }
        if (rb < 4) {
            int i = rb*256 + threadIdx.x;
            if (i < M1) g_rowsum[i] = 0.f;
        }
    }
}

// ================= mma.sync GEMM (multistage, 1 sync/iter) =================
// MODE 0: conv1 implicit GEMM — A gathered from fp16 canvas (zero-fill halo),
//         epilogue relu(+bias) -> g_A2 fp16.
// MODE 1: conv2 — A = g_A2, epilogue +bias -> outp fp32 + rowsum atomics.
template<int BM, int BN, int K, int MODE, int STAGES, int MW>
__global__ __launch_bounds__(256) void gemm_mma(const float* __restrict__ bias,
                                                float* __restrict__ outp)
{
    extern __shared__ __align__(1024) char smem[];
    constexpr int NKB = K / 64;
    constexpr int ASZ = BM*128;
    constexpr int BSZ = BN*128;
    constexpr int SSZ = ASZ + BSZ;
    constexpr int NW  = 8/MW;
    constexpr int WMS = BM/MW;
    constexpr int MI  = WMS/16;
    constexpr int WNS = BN/NW;
    constexpr int NJ  = WNS/8;
    constexpr int AIT = BM*8/256;
    constexpr int BIT = BN*8/256;

    const uint32_t sbase = smem_to_u32(smem);
    const int tid  = threadIdx.x;
    const int lane = tid & 31, wid = tid >> 5;
    const int warpM = wid % MW, warpN = wid / MW;
    const int bn = blockIdx.x * BN, bm = blockIdx.y * BM;
    const int wm = warpM*WMS, wn = warpN*WNS;

    const __half* __restrict__ Bm = (MODE == 0) ? g_B1 : g_B2;

    // hoisted per-thread A-loader state
    uint32_t dstA[AIT];
    int aoff[AIT];
    int ihb[AIT], iwb[AIT];
    bool mok[AIT];
    #pragma unroll
    for (int i = 0; i < AIT; i++) {
        int c = tid + i*256;
        int r = c >> 3, u = c & 7;
        int m = bm + r;
        dstA[i] = SWZ(r*128 + u*16);
        mok[i] = m < M1;
        if (MODE == 0) {
            int mc = mok[i] ? m : 0;
            int b = mc / 100, p = mc - b*100;
            int hp = p / 10, wp = p - hp*10;
            ihb[i] = 4*hp - 1; iwb[i] = 4*wp - 1;
            aoff[i] = b*(GH*GW*CF) + u*8;
        } else {
            aoff[i] = (mok[i] ? m : 0)*K + u*8;
        }
    }

    // hoisted B-loader state
    uint32_t dstB[BIT];
    int boff[BIT];
    #pragma unroll
    for (int i = 0; i < BIT; i++) {
        int c = tid + i*256;
        int r = c >> 3, u = c & 7;
        dstB[i] = ASZ + SWZ(r*128 + u*16);
        boff[i] = (bn + r)*K + u*8;
    }

    float d[MI][NJ][4];
    #pragma unroll
    for (int mi=0;mi<MI;mi++)
        #pragma unroll
        for (int nj=0;nj<NJ;nj++)
            #pragma unroll
            for (int c=0;c<4;c++) d[mi][nj][c] = 0.f;

    auto load_tile = [&](int kb, int slot) {
        const uint32_t base = sbase + (uint32_t)slot*SSZ;
        int koff = kb*64;
        if (MODE == 0) {
            int tap = kb >> 2, ci0 = (kb & 3) << 6;
            int kh = tap / 3, kw = tap - 3*kh;
            #pragma unroll
            for (int i = 0; i < AIT; i++) {
                int ih = ihb[i] + kh, iw = iwb[i] + kw;
                bool ok = mok[i] && (unsigned)ih < (unsigned)GH && (unsigned)iw < (unsigned)GW;
                const __half* src = g_canvas_h +
                    (ok ? (aoff[i] + (ih*GW + iw)*CF + ci0) : 0);
                cpa16p(base + dstA[i], src, ok ? 16u : 0u);
            }
        } else {
            #pragma unroll
            for (int i = 0; i < AIT; i++)
                cpa16(base + dstA[i], g_A2 + (size_t)aoff[i] + koff);
        }
        #pragma unroll
        for (int i = 0; i < BIT; i++)
            cpa16(base + dstB[i], Bm + (size_t)boff[i] + koff);
    };

    // prefill STAGES-1 tiles
    #pragma unroll
    for (int s = 0; s < STAGES-1; s++) { load_tile(s, s); CP_COMMIT(); }

    for (int kb = 0; kb < NKB; kb++) {
        asm volatile("cp.async.wait_group %0;" :: "n"(STAGES-2) : "memory");
        __syncthreads();

        int nk = kb + STAGES-1;
        if (nk < NKB) load_tile(nk, nk % STAGES);
        CP_COMMIT();

        const uint32_t base = sbase + (uint32_t)(kb % STAGES)*SSZ;
        const uint32_t ab = base, bb = base + ASZ;
        #pragma unroll
        for (int kc = 0; kc < 4; kc++) {
            uint32_t afr[MI][4];
            #pragma unroll
            for (int mi = 0; mi < MI; mi++) {
                int row  = wm + mi*16 + (lane & 15);
                int unit = kc*2 + (lane >> 4);
                ldsm4(afr[mi], ab + SWZ(row*128 + unit*16));
            }
            uint32_t bfr[NJ][2];
            #pragma unroll
            for (int p = 0; p < NJ/2; p++) {
                int row  = wn + p*16 + (lane & 7) + ((lane & 16) ? 8 : 0);
                int unit = kc*2 + ((lane >> 3) & 1);
                uint32_t t[4];
                ldsm4(t, bb + SWZ(row*128 + unit*16));
                bfr[p*2][0]   = t[0]; bfr[p*2][1]   = t[1];
                bfr[p*2+1][0] = t[2]; bfr[p*2+1][1] = t[3];
            }
            #pragma unroll
            for (int mi = 0; mi < MI; mi++)
                #pragma unroll
                for (int nj = 0; nj < NJ; nj++)
                    mma16816(d[mi][nj], afr[mi], bfr[nj]);
        }
    }

    // ---------------- epilogue ----------------
    #pragma unroll
    for (int mi = 0; mi < MI; mi++) {
        int m0 = bm + wm + mi*16 + (lane >> 2);
        #pragma unroll
        for (int h = 0; h < 2; h++) {
            int m = m0 + h*8;
            bool ok = m < M1;
            float rsum = 0.f;
            #pragma unroll
            for (int nj = 0; nj < NJ; nj++) {
                int n0 = bn + wn + nj*8 + (lane & 3)*2;
                float v0 = d[mi][nj][h*2+0] + __ldg(bias + n0);
                float v1 = d[mi][nj][h*2+1] + __ldg(bias + n0 + 1);
                if (MODE == 0) {
                    if (ok) {
                        __half hh[2];
                        hh[0] = __float2half_rn(fmaxf(v0, 0.f));
                        hh[1] = __float2half_rn(fmaxf(v1, 0.f));
                        *(uint32_t*)(g_A2 + (size_t)m*K2 + n0) = *(uint32_t*)hh;
                    }
                } else {
                    rsum += v0 + v1;
                    if (ok) {
                        float2 o; o.x = v0; o.y = v1;
                        *(float2*)(outp + (size_t)m*N2 + n0) = o;
                    }
                }
            }
            if (MODE == 1) {
                rsum += __shfl_xor_sync(0xffffffffu, rsum, 1);
                rsum += __shfl_xor_sync(0xffffffffu, rsum, 2);
                if ((lane & 3) == 0 && ok)
                    atomicAdd(&g_rowsum[m], rsum);
            }
        }
    }
}

// ================= fused back end: single block, parallel loads ==========
__global__ __launch_bounds__(256) void fused_post(float* __restrict__ out,
                                                  float* __restrict__ tail,
                                                  int has_tail) {
    __shared__ unsigned char okf[M1];
    __shared__ int nzero;
    int t = threadIdx.x;
    if (t == 0) nzero = 0;
    __syncthreads();
    #pragma unroll
    for (int i = 0; i < 4; i++) {                 // parallel independent loads
        int m = t + i*256;
        if (m < M1) {
            bool ok = (g_rowsum[m] != 0.0f);
            okf[m] = ok ? 1 : 0;
            if (!ok) atomicAdd(&nzero, 1);
        }
    }
    __syncthreads();

    if (has_tail && t < 256) {
        int b = t >> 5, lane = t & 31;
        if (b < BATCH) {
            int cnt = 0;
            for (int i = lane; i < 100; i += 32) cnt += okf[b*100 + i];
            #pragma unroll
            for (int o = 16; o; o >>= 1) cnt += __shfl_xor_sync(0xffffffffu, cnt, o);
            if (lane == 0) tail[b] = (float)(cnt + 1);
        }
    }

    if (nzero > 0) {                              // rare path
        for (int m = 0; m < M1; m++) {
            if (!okf[m]) {
                float* row = out + (size_t)m * N2;
                for (int i = t; i < N2; i += 256) row[i] = 0.0f;
            }
        }
    }
}

// ================= launch =================
extern "C" void kernel_launch(void* const* d_in, const int* in_sizes, int n_in,
                              void* d_out, int out_size) {
    const float* voxels     = (const float*)d_in[0];
    const int*   num_points = (const int*)  d_in[1];
    const int*   coors      = (const int*)  d_in[2];
    const float* w_pfn      = (const float*)d_in[3];
    const float* bn_gamma   = (const float*)d_in[4];
    const float* bn_beta    = (const float*)d_in[5];
    const float* bn_mean    = (const float*)d_in[6];
    const float* bn_var     = (const float*)d_in[7];
    const float* conv1_w    = (const float*)d_in[8];
    const float* conv1_b    = (const float*)d_in[9];
    const float* conv2_w    = (const float*)d_in[10];
    const float* conv2_b    = (const float*)d_in[11];
    float* out = (float*)d_out;

    // gemm1: BM64/BN128, 2 stages -> 48KB; grid 8x14=112 (single wave)
    // gemm2: BM64/BN128, 2 stages -> 48KB; grid 32x14=448 (R9-proven config)
    constexpr int SMEM12 = (64*128 + 128*128) * 2;   // 49152
    static bool attr_done = false;
    if (!attr_done) {
        cudaFuncSetAttribute(gemm_mma<64, 128, K1, 0, 2, 2>, cudaFuncAttributeMaxDynamicSharedMemorySize, SMEM12);
        cudaFuncSetAttribute(gemm_mma<64, 128, K2, 1, 2, 2>, cudaFuncAttributeMaxDynamicSharedMemorySize, SMEM12);
        attr_done = true;
    }

    fused_pre<<<NPFN + N1 + NW2B, 256>>>(voxels, num_points, coors, w_pfn,
                                         bn_gamma, bn_beta, bn_mean, bn_var,
                                         conv1_w, conv2_w);

    gemm_mma<64, 128, K1, 0, 2, 2><<<dim3(N1/128, MPAD/64), 256, SMEM12>>>(conv1_b, nullptr);
    gemm_mma<64, 128, K2, 1, 2, 2><<<dim3(N2/128, MPAD/64), 256, SMEM12>>>(conv2_b, out);

    int has_tail = (out_size >= OUT_MAIN + BATCH) ? 1 : 0;
    fused_post<<<1, 256>>>(out, out + OUT_MAIN, has_tail);
}

// round 17
// speedup vs baseline: 1.0919x; 1.0919x over previous
#include <cuda_runtime.h>
#include <cuda_fp16.h>
#include <cstdint>
#include <math.h>

// ---------------- problem constants ----------------
#define BATCH   8
#define GH      40
#define GW      40
#define MPIL    (BATCH*GH*GW)      // 12800 pillars
#define NPTS    32
#define CIN     6
#define CF      256
#define NFEAT   12

#define M1      800
#define MPAD    896                // padded M for guard-free loads
#define N1      1024
#define K1      2304               // 9 taps * 256
#define N2      4096
#define K2      1024
#define OUT_MAIN (M1*N2)           // 3276800

#define NPFN    (MPIL/2)           // 6400 pfn blocks (2 pillars each)
#define NW2B    (N2*K2/4/256)      // 4096 w2-convert blocks

// ---------------- device scratch ----------------
__device__ __half  g_canvas_h[MPIL*CF];   // NHWC fp16 canvas
__device__ __half  g_B1[N1*K1];
__device__ __half  g_A2[MPAD*K2];
__device__ __half  g_B2[N2*K2];
__device__ float   g_rowsum[M1];

// ================= helpers =================
__device__ __forceinline__ uint32_t smem_to_u32(const void* p) {
    uint32_t a;
    asm("{ .reg .u64 t; cvta.to.shared.u64 t, %1; cvt.u32.u64 %0, t; }" : "=r"(a) : "l"(p));
    return a;
}
#define SWZ(x) ((uint32_t)(x) ^ (((uint32_t)(x) >> 3) & 0x70))

__device__ __forceinline__ void cpa16(uint32_t dst, const void* src) {
    asm volatile("cp.async.cg.shared.global [%0], [%1], 16;"
                 :: "r"(dst), "l"(src) : "memory");
}
__device__ __forceinline__ void cpa16p(uint32_t dst, const void* src, uint32_t srcsize) {
    asm volatile("cp.async.cg.shared.global [%0], [%1], 16, %2;"
                 :: "r"(dst), "l"(src), "r"(srcsize) : "memory");
}
#define CP_COMMIT() asm volatile("cp.async.commit_group;" ::: "memory")

__device__ __forceinline__ void ldsm4(uint32_t* r, uint32_t addr) {
    asm volatile("ldmatrix.sync.aligned.m8n8.x4.shared.b16 {%0,%1,%2,%3}, [%4];"
        : "=r"(r[0]), "=r"(r[1]), "=r"(r[2]), "=r"(r[3]) : "r"(addr));
}
__device__ __forceinline__ void mma16816(float* d, const uint32_t* a, const uint32_t* b) {
    asm volatile(
        "mma.sync.aligned.m16n8k16.row.col.f32.f16.f16.f32 "
        "{%0,%1,%2,%3}, {%4,%5,%6,%7}, {%8,%9}, {%0,%1,%2,%3};"
        : "+f"(d[0]), "+f"(d[1]), "+f"(d[2]), "+f"(d[3])
        : "r"(a[0]), "r"(a[1]), "r"(a[2]), "r"(a[3]), "r"(b[0]), "r"(b[1]));
}

// packed fp32x2 (sm_100+ family feature, legal at compute_103)
#define PACK2(out, lo, hi)  asm("mov.b64 %0, {%1, %2};" : "=l"(out) : "f"(lo), "f"(hi))
#define BCAST2(out, v)      asm("mov.b64 %0, {%1, %1};" : "=l"(out) : "f"(v))
#define UNPACK2(lo, hi, in) asm("mov.b64 {%0, %1}, %2;" : "=f"(lo), "=f"(hi) : "l"(in))
#define FMA2(acc, a, b)     asm("fma.rn.f32x2 %0, %1, %2, %0;" : "+l"(acc) : "l"(a), "l"(b))
#define ADD2(out, a, b)     asm("add.rn.f32x2 %0, %1, %2;" : "=l"(out) : "l"(a), "l"(b))

// ================= fused front end: PFN + w1 transpose + w2 convert ======
__global__ __launch_bounds__(256) void fused_pre(
    const float* __restrict__ voxels, const int* __restrict__ num_points,
    const int* __restrict__ coors,    const float* __restrict__ w,
    const float* __restrict__ bn_gamma, const float* __restrict__ bn_beta,
    const float* __restrict__ bn_mean,  const float* __restrict__ bn_var,
    const float* __restrict__ w1, const float* __restrict__ w2)
{
    __shared__ float sbuf[K1];           // w1 path: full row; pfn path: feats+smean
    int blk = blockIdx.x;

    if (blk < NPFN) {
        // ---- PFN ----
        float* feats = sbuf;             // [sub][n][d] -> sub*384 + n*12 + d
        float* smean = sbuf + 768;       // [sub*3 + j]
        int sub = threadIdx.x >> 7;
        int f   = threadIdx.x & 127;
        int m   = blk*2 + sub;

        int np = num_points[m];
        const float* vox = voxels + (size_t)m * NPTS * CIN;

        float x=0.f, y=0.f, z=0.f, msk=0.f;
        if (f < NPTS) {
            int n = f;
            msk = (n < np) ? 1.0f : 0.0f;
            x = vox[n*CIN+0]; y = vox[n*CIN+1]; z = vox[n*CIN+2];
            float mx=x*msk, my=y*msk, mz=z*msk;
            #pragma unroll
            for (int o = 16; o; o >>= 1) {
                mx += __shfl_xor_sync(0xffffffffu, mx, o);
                my += __shfl_xor_sync(0xffffffffu, my, o);
                mz += __shfl_xor_sync(0xffffffffu, mz, o);
            }
            if (n == 0) {
                float inv = 1.0f / (float)np;
                smean[sub*3+0]=mx*inv; smean[sub*3+1]=my*inv; smean[sub*3+2]=mz*inv;
            }
        }
        __syncthreads();
        if (f < NPTS) {
            int n = f;
            float cx = (float)coors[m*4+3]*0.025f + (0.0125f - 0.5f);
            float cy = (float)coors[m*4+2]*0.025f + (0.0125f - 0.5f);
            float cz = (float)coors[m*4+1]*1.0f + 0.5f;
            float* fr = feats + sub*384 + n*12;
            fr[0]=x*msk;  fr[1]=y*msk;  fr[2]=z*msk;
            fr[3]=vox[n*CIN+3]*msk; fr[4]=vox[n*CIN+4]*msk; fr[5]=vox[n*CIN+5]*msk;
            fr[6]=(x-smean[sub*3+0])*msk; fr[7]=(y-smean[sub*3+1])*msk; fr[8]=(z-smean[sub*3+2])*msk;
            fr[9]=(x-cx)*msk; fr[10]=(y-cy)*msk; fr[11]=(z-cz)*msk;
        }
        __syncthreads();

        int f1 = f + 128;
        float sc0 = bn_gamma[f]  * rsqrtf(bn_var[f]  + 1e-3f);
        float sc1 = bn_gamma[f1] * rsqrtf(bn_var[f1] + 1e-3f);
        float bt0 = bn_beta[f]  - bn_mean[f]  * sc0;
        float bt1 = bn_beta[f1] - bn_mean[f1] * sc1;
        unsigned long long w2v[NFEAT], bt2, zero2;
        #pragma unroll
        for (int d = 0; d < NFEAT; d++)
            PACK2(w2v[d], w[d*CF + f] * sc0, w[d*CF + f1] * sc1);
        PACK2(bt2, bt0, bt1);
        PACK2(zero2, 0.f, 0.f);

        float vmax0 = (np < NPTS) ? fmaxf(bt0, 0.f) : 0.f;
        float vmax1 = (np < NPTS) ? fmaxf(bt1, 0.f) : 0.f;
        const float* fb = feats + sub*384;
        #pragma unroll 2
        for (int n = 0; n < np; n++) {
            // two independent 6-FMA2 chains halve the serial latency
            unsigned long long acc_a = bt2, acc_b = zero2;
            #pragma unroll
            for (int d = 0; d < 6; d++) {
                unsigned long long fa, fc;
                BCAST2(fa, fb[n*12 + d]);
                FMA2(acc_a, fa, w2v[d]);
                BCAST2(fc, fb[n*12 + 6 + d]);
                FMA2(acc_b, fc, w2v[6 + d]);
            }
            unsigned long long acc;
            ADD2(acc, acc_a, acc_b);
            float h0, h1; UNPACK2(h0, h1, acc);
            vmax0 = fmaxf(vmax0, h0);
            vmax1 = fmaxf(vmax1, h1);
        }

        int b = coors[m*4+0], yy = coors[m*4+2], xx = coors[m*4+3];
        size_t px = (((size_t)b*GH + yy)*GW + xx)*CF;
        g_canvas_h[px + f]  = __float2half_rn(vmax0);
        g_canvas_h[px + f1] = __float2half_rn(vmax1);
    } else if (blk < NPFN + N1) {
        // ---- w1 transpose ----
        int o = blk - NPFN;
        const float* src = w1 + (size_t)o*K1;
        #pragma unroll
        for (int i = threadIdx.x; i < K1; i += 256) sbuf[i] = src[i];
        __syncthreads();
        #pragma unroll
        for (int i = threadIdx.x; i < K1; i += 256) {
            int tap = i >> 8, ci = i & 255;
            g_B1[(size_t)o*K1 + i] = __float2half_rn(sbuf[ci*9 + tap]);
        }
    } else {
        // ---- w2 convert (+ rowsum clear) ----
        int rb = blk - NPFN - N1;
        int t = rb*256 + threadIdx.x;
        if (t < N2*K2/4) {
            float4 v = *(const float4*)(w2 + (size_t)t*4);
            __half h[4];
            h[0]=__float2half_rn(v.x); h[1]=__float2half_rn(v.y);
            h[2]=__float2half_rn(v.z); h[3]=__float2half_rn(v.w);
            *(uint2*)(g_B2 + (size_t)t*4) = *(uint2*)h;
        }
        if (rb < 4) {
            int i = rb*256 + threadIdx.x;
            if (i < M1) g_rowsum[i] = 0.f;
        }
    }
}

// ================= mma.sync GEMM (multistage, 1 sync/iter) =================
// MODE 0: conv1 implicit GEMM — A gathered from fp16 canvas (zero-fill halo),
//         epilogue relu(+bias) -> g_A2 fp16.
// MODE 1: conv2 — A = g_A2, epilogue +bias -> outp fp32 + rowsum atomics.
template<int BM, int BN, int K, int MODE, int STAGES, int MW>
__global__ __launch_bounds__(256) void gemm_mma(const float* __restrict__ bias,
                                                float* __restrict__ outp)
{
    extern __shared__ __align__(1024) char smem[];
    constexpr int NKB = K / 64;
    constexpr int ASZ = BM*128;
    constexpr int BSZ = BN*128;
    constexpr int SSZ = ASZ + BSZ;
    constexpr int NW  = 8/MW;
    constexpr int WMS = BM/MW;
    constexpr int MI  = WMS/16;
    constexpr int WNS = BN/NW;
    constexpr int NJ  = WNS/8;
    constexpr int AIT = BM*8/256;
    constexpr int BIT = BN*8/256;

    const uint32_t sbase = smem_to_u32(smem);
    const int tid  = threadIdx.x;
    const int lane = tid & 31, wid = tid >> 5;
    const int warpM = wid % MW, warpN = wid / MW;
    const int bn = blockIdx.x * BN, bm = blockIdx.y * BM;
    const int wm = warpM*WMS, wn = warpN*WNS;

    const __half* __restrict__ Bm = (MODE == 0) ? g_B1 : g_B2;

    // hoisted per-thread A-loader state
    uint32_t dstA[AIT];
    int aoff[AIT];
    int ihb[AIT], iwb[AIT];
    bool mok[AIT];
    #pragma unroll
    for (int i = 0; i < AIT; i++) {
        int c = tid + i*256;
        int r = c >> 3, u = c & 7;
        int m = bm + r;
        dstA[i] = SWZ(r*128 + u*16);
        mok[i] = m < M1;
        if (MODE == 0) {
            int mc = mok[i] ? m : 0;
            int b = mc / 100, p = mc - b*100;
            int hp = p / 10, wp = p - hp*10;
            ihb[i] = 4*hp - 1; iwb[i] = 4*wp - 1;
            aoff[i] = b*(GH*GW*CF) + u*8;
        } else {
            aoff[i] = (mok[i] ? m : 0)*K + u*8;
        }
    }

    // hoisted B-loader state
    uint32_t dstB[BIT];
    int boff[BIT];
    #pragma unroll
    for (int i = 0; i < BIT; i++) {
        int c = tid + i*256;
        int r = c >> 3, u = c & 7;
        dstB[i] = ASZ + SWZ(r*128 + u*16);
        boff[i] = (bn + r)*K + u*8;
    }

    float d[MI][NJ][4];
    #pragma unroll
    for (int mi=0;mi<MI;mi++)
        #pragma unroll
        for (int nj=0;nj<NJ;nj++)
            #pragma unroll
            for (int c=0;c<4;c++) d[mi][nj][c] = 0.f;

    auto load_tile = [&](int kb, int slot) {
        const uint32_t base = sbase + (uint32_t)slot*SSZ;
        int koff = kb*64;
        if (MODE == 0) {
            int tap = kb >> 2, ci0 = (kb & 3) << 6;
            int kh = tap / 3, kw = tap - 3*kh;
            #pragma unroll
            for (int i = 0; i < AIT; i++) {
                int ih = ihb[i] + kh, iw = iwb[i] + kw;
                bool ok = mok[i] && (unsigned)ih < (unsigned)GH && (unsigned)iw < (unsigned)GW;
                const __half* src = g_canvas_h +
                    (ok ? (aoff[i] + (ih*GW + iw)*CF + ci0) : 0);
                cpa16p(base + dstA[i], src, ok ? 16u : 0u);
            }
        } else {
            #pragma unroll
            for (int i = 0; i < AIT; i++)
                cpa16(base + dstA[i], g_A2 + (size_t)aoff[i] + koff);
        }
        #pragma unroll
        for (int i = 0; i < BIT; i++)
            cpa16(base + dstB[i], Bm + (size_t)boff[i] + koff);
    };

    // prefill STAGES-1 tiles
    #pragma unroll
    for (int s = 0; s < STAGES-1; s++) { load_tile(s, s); CP_COMMIT(); }

    for (int kb = 0; kb < NKB; kb++) {
        asm volatile("cp.async.wait_group %0;" :: "n"(STAGES-2) : "memory");
        __syncthreads();

        int nk = kb + STAGES-1;
        if (nk < NKB) load_tile(nk, nk % STAGES);
        CP_COMMIT();

        const uint32_t base = sbase + (uint32_t)(kb % STAGES)*SSZ;
        const uint32_t ab = base, bb = base + ASZ;
        #pragma unroll
        for (int kc = 0; kc < 4; kc++) {
            uint32_t afr[MI][4];
            #pragma unroll
            for (int mi = 0; mi < MI; mi++) {
                int row  = wm + mi*16 + (lane & 15);
                int unit = kc*2 + (lane >> 4);
                ldsm4(afr[mi], ab + SWZ(row*128 + unit*16));
            }
            uint32_t bfr[NJ][2];
            #pragma unroll
            for (int p = 0; p < NJ/2; p++) {
                int row  = wn + p*16 + (lane & 7) + ((lane & 16) ? 8 : 0);
                int unit = kc*2 + ((lane >> 3) & 1);
                uint32_t t[4];
                ldsm4(t, bb + SWZ(row*128 + unit*16));
                bfr[p*2][0]   = t[0]; bfr[p*2][1]   = t[1];
                bfr[p*2+1][0] = t[2]; bfr[p*2+1][1] = t[3];
            }
            #pragma unroll
            for (int mi = 0; mi < MI; mi++)
                #pragma unroll
                for (int nj = 0; nj < NJ; nj++)
                    mma16816(d[mi][nj], afr[mi], bfr[nj]);
        }
    }

    // ---------------- epilogue ----------------
    #pragma unroll
    for (int mi = 0; mi < MI; mi++) {
        int m0 = bm + wm + mi*16 + (lane >> 2);
        #pragma unroll
        for (int h = 0; h < 2; h++) {
            int m = m0 + h*8;
            bool ok = m < M1;
            float rsum = 0.f;
            #pragma unroll
            for (int nj = 0; nj < NJ; nj++) {
                int n0 = bn + wn + nj*8 + (lane & 3)*2;
                float v0 = d[mi][nj][h*2+0] + __ldg(bias + n0);
                float v1 = d[mi][nj][h*2+1] + __ldg(bias + n0 + 1);
                if (MODE == 0) {
                    if (ok) {
                        __half hh[2];
                        hh[0] = __float2half_rn(fmaxf(v0, 0.f));
                        hh[1] = __float2half_rn(fmaxf(v1, 0.f));
                        *(uint32_t*)(g_A2 + (size_t)m*K2 + n0) = *(uint32_t*)hh;
                    }
                } else {
                    rsum += v0 + v1;
                    if (ok) {
                        float2 o; o.x = v0; o.y = v1;
                        *(float2*)(outp + (size_t)m*N2 + n0) = o;
                    }
                }
            }
            if (MODE == 1) {
                rsum += __shfl_xor_sync(0xffffffffu, rsum, 1);
                rsum += __shfl_xor_sync(0xffffffffu, rsum, 2);
                if ((lane & 3) == 0 && ok)
                    atomicAdd(&g_rowsum[m], rsum);
            }
        }
    }
}

// ================= fused back end: single block, parallel loads ==========
__global__ __launch_bounds__(256) void fused_post(float* __restrict__ out,
                                                  float* __restrict__ tail,
                                                  int has_tail) {
    __shared__ unsigned char okf[M1];
    __shared__ int nzero;
    int t = threadIdx.x;
    if (t == 0) nzero = 0;
    __syncthreads();
    #pragma unroll
    for (int i = 0; i < 4; i++) {                 // parallel independent loads
        int m = t + i*256;
        if (m < M1) {
            bool ok = (g_rowsum[m] != 0.0f);
            okf[m] = ok ? 1 : 0;
            if (!ok) atomicAdd(&nzero, 1);
        }
    }
    __syncthreads();

    if (has_tail && t < 256) {
        int b = t >> 5, lane = t & 31;
        if (b < BATCH) {
            int cnt = 0;
            for (int i = lane; i < 100; i += 32) cnt += okf[b*100 + i];
            #pragma unroll
            for (int o = 16; o; o >>= 1) cnt += __shfl_xor_sync(0xffffffffu, cnt, o);
            if (lane == 0) tail[b] = (float)(cnt + 1);
        }
    }

    if (nzero > 0) {                              // rare path
        for (int m = 0; m < M1; m++) {
            if (!okf[m]) {
                float* row = out + (size_t)m * N2;
                for (int i = t; i < N2; i += 256) row[i] = 0.0f;
            }
        }
    }
}

// ================= launch =================
extern "C" void kernel_launch(void* const* d_in, const int* in_sizes, int n_in,
                              void* d_out, int out_size) {
    const float* voxels     = (const float*)d_in[0];
    const int*   num_points = (const int*)  d_in[1];
    const int*   coors      = (const int*)  d_in[2];
    const float* w_pfn      = (const float*)d_in[3];
    const float* bn_gamma   = (const float*)d_in[4];
    const float* bn_beta    = (const float*)d_in[5];
    const float* bn_mean    = (const float*)d_in[6];
    const float* bn_var     = (const float*)d_in[7];
    const float* conv1_w    = (const float*)d_in[8];
    const float* conv1_b    = (const float*)d_in[9];
    const float* conv2_w    = (const float*)d_in[10];
    const float* conv2_b    = (const float*)d_in[11];
    float* out = (float*)d_out;

    // gemm1: BM64/BN128, 2 stages -> 48KB; grid 8x14=112 (single wave)
    // gemm2: BM64/BN128, 2 stages -> 48KB; grid 32x14=448 (R9-proven config)
    constexpr int SMEM12 = (64*128 + 128*128) * 2;   // 49152
    static bool attr_done = false;
    if (!attr_done) {
        cudaFuncSetAttribute(gemm_mma<64, 128, K1, 0, 2, 2>, cudaFuncAttributeMaxDynamicSharedMemorySize, SMEM12);
        cudaFuncSetAttribute(gemm_mma<64, 128, K2, 1, 2, 2>, cudaFuncAttributeMaxDynamicSharedMemorySize, SMEM12);
        attr_done = true;
    }

    fused_pre<<<NPFN + N1 + NW2B, 256>>>(voxels, num_points, coors, w_pfn,
                                         bn_gamma, bn_beta, bn_mean, bn_var,
                                         conv1_w, conv2_w);

    gemm_mma<64, 128, K1, 0, 2, 2><<<dim3(N1/128, MPAD/64), 256, SMEM12>>>(conv1_b, nullptr);
    gemm_mma<64, 128, K2, 1, 2, 2><<<dim3(N2/128, MPAD/64), 256, SMEM12>>>(conv2_b, out);

    int has_tail = (out_size >= OUT_MAIN + BATCH) ? 1 : 0;
    fused_post<<<1, 256>>>(out, out + OUT_MAIN, has_tail);
}